// round 10
// baseline (speedup 1.0000x reference)
#include <cuda_runtime.h>

typedef unsigned long long ull;

#define MD 100
#define HD 512
#define NP 10000
#define MN 51200

// ---------------- device scratch ----------------
__device__ __align__(16) float g_child0[MD*HD];
__device__ __align__(16) float g_child1[MD*HD];
__device__ __align__(16) float g_child2[MD*HD];
__device__ __align__(16) float g_A[MD*HD];
__device__ __align__(16) float g_B[MD*HD];
__device__ __align__(16) float g_Ai[MD*HD];
__device__ __align__(16) float g_Bj[MD*HD];
__device__ __align__(16) float g_h[MD*HD];
__device__ __align__(16) float g_Ce0[NP*HD];
__device__ __align__(16) float g_Ce1[NP*HD];
__device__ __align__(16) float g_gpart[4*MN];
__device__ __align__(16) float g_part[16*MN];
__device__ __align__(16) float g_partS[4*5700];
__device__ int   g_nodeok[MD];
__device__ int   g_pairlist[NP];
__device__ int   g_paircnt;

__device__ __forceinline__ ull ffma2(ull a, ull b, ull c){
    ull d;
    asm("fma.rn.f32x2 %0, %1, %2, %3;" : "=l"(d) : "l"(a), "l"(b), "l"(c));
    return d;
}
__device__ __forceinline__ ull dup2(float v){
    unsigned u = __float_as_uint(v);
    return ((ull)u << 32) | (ull)u;
}
__device__ __forceinline__ float* sel_buf(int code){
    switch (code){
        case 0: return g_A;      case 1: return g_B;
        case 2: return g_Ai;     case 3: return g_Bj;
        case 4: return g_h;      case 5: return g_child0;
        case 6: return g_child1; default: return g_child2;
    }
}
__device__ __forceinline__ float fetchA(int code, int m, int k){
    if (code == 9){   // virtual concat [child0|child1|child2]
        int q = k >> 9, kk = k & 511;
        const float* s = (q==0) ? g_child0 : (q==1) ? g_child1 : g_child2;
        return s[m*HD + kk];
    }
    return sel_buf(code)[m*HD + k];
}

// ---------------- parent GEMV: float4, split-K. grid (50,4), 256 thr ----------------
__global__ void k_gemv_part(const float* __restrict__ pf, const float* __restrict__ Wp){
    __shared__ float pfs[128];
    const int z = blockIdx.y;
    const int c4 = blockIdx.x*256 + threadIdx.x;
    if (threadIdx.x < 128) pfs[threadIdx.x] = pf[z*128 + threadIdx.x];
    __syncthreads();
    const float4* w = (const float4*)Wp + (long long)(z*128)*12800 + c4;
    float4 a = make_float4(0.f,0.f,0.f,0.f);
    #pragma unroll 8
    for (int k=0; k<128; k++){
        float4 wv = w[(long long)k*12800];
        float s = pfs[k];
        a.x += s*wv.x; a.y += s*wv.y; a.z += s*wv.z; a.w += s*wv.w;
    }
    ((float4*)g_gpart)[z*12800 + c4] = a;
}

// finisher + exists logits fused. grid 100, 128 thr.
__global__ void k_gemv_fin(const float* __restrict__ bp, const float* __restrict__ Wx,
                           const float* __restrict__ bx, float* __restrict__ out_ex){
    __shared__ float red[4];
    const int m = blockIdx.x, t = threadIdx.x;
    const int c4 = m*128 + t;
    const float4* gp = (const float4*)g_gpart;
    float4 s0 = gp[c4], s1 = gp[12800+c4], s2 = gp[2*12800+c4], s3 = gp[3*12800+c4];
    float4 b  = ((const float4*)bp)[c4];
    float4 v;
    v.x = fmaxf(s0.x+s1.x+s2.x+s3.x+b.x, 0.f);
    v.y = fmaxf(s0.y+s1.y+s2.y+s3.y+b.y, 0.f);
    v.z = fmaxf(s0.z+s1.z+s2.z+s3.z+b.z, 0.f);
    v.w = fmaxf(s0.w+s1.w+s2.w+s3.w+b.w, 0.f);
    ((float4*)g_child0)[c4] = v;
    float4 wx = ((const float4*)Wx)[t];
    float p = v.x*wx.x + v.y*wx.y + v.z*wx.z + v.w*wx.w;
    #pragma unroll
    for (int o=16; o; o>>=1) p += __shfl_xor_sync(~0u, p, o);
    if ((t & 31) == 0) red[t>>5] = p;
    __syncthreads();
    if (t == 0){
        float vv = red[0]+red[1]+red[2]+red[3] + bx[0];
        out_ex[m]   = vv;
        g_nodeok[m] = (vv > 0.f) ? 1 : 0;
        g_paircnt   = (m == 0) ? g_paircnt : g_paircnt;
        if (m == 0) g_paircnt = 0;
    }
}

// ---------------- split-K multi-job GEMM partials, pipelined ----------------
__global__ void k_gp(int acodes, int Klen, int KS,
                     const float* __restrict__ B0, const float* __restrict__ B1,
                     const float* __restrict__ B2, const float* __restrict__ B3){
    __shared__ ull   As2[16*33];
    __shared__ float Bs[16*68];
    const int KSL = Klen / KS;
    const int job = blockIdx.z / KS, sl = blockIdx.z % KS;
    const int Acode = (acodes >> (8*job)) & 255;
    const float* B = (job==0)?B0:(job==1)?B1:(job==2)?B2:B3;
    const int kb = sl*KSL;
    const int n0 = blockIdx.x*64, m0 = blockIdx.y*32;
    const int t = threadIdx.x, tr = t>>4, tc = t&15;
    const int ar0 = t>>4, ak = t&15, ar1 = ar0+16;
    const int bn = t&63, bk0 = t>>6;
    const int gm0 = m0+ar0, gm1 = m0+ar1;
    float pa0, pa1, pb0, pb1, pb2, pb3;
    {
        int k = kb + ak;
        pa0 = (gm0 < MD) ? fetchA(Acode, gm0, k) : 0.f;
        pa1 = (gm1 < MD) ? fetchA(Acode, gm1, k) : 0.f;
        int kB = kb + bk0;
        pb0 = B[(kB   )*HD + n0+bn]; pb1 = B[(kB+4 )*HD + n0+bn];
        pb2 = B[(kB+8 )*HD + n0+bn]; pb3 = B[(kB+12)*HD + n0+bn];
    }
    ull acc[2][2] = {};
    const int nkt = KSL/16;
    for (int kt=0; kt<nkt; kt++){
        As2[ak*33 + ar0] = dup2(pa0);
        As2[ak*33 + ar1] = dup2(pa1);
        Bs[(bk0   )*68 + bn] = pb0;
        Bs[(bk0+4 )*68 + bn] = pb1;
        Bs[(bk0+8 )*68 + bn] = pb2;
        Bs[(bk0+12)*68 + bn] = pb3;
        __syncthreads();
        if (kt+1 < nkt){
            int k = kb + (kt+1)*16 + ak;
            pa0 = (gm0 < MD) ? fetchA(Acode, gm0, k) : 0.f;
            pa1 = (gm1 < MD) ? fetchA(Acode, gm1, k) : 0.f;
            int kB = kb + (kt+1)*16 + bk0;
            pb0 = B[(kB   )*HD + n0+bn]; pb1 = B[(kB+4 )*HD + n0+bn];
            pb2 = B[(kB+8 )*HD + n0+bn]; pb3 = B[(kB+12)*HD + n0+bn];
        }
        #pragma unroll
        for (int k=0; k<16; k++){
            ull a0 = As2[k*33+tr], a1 = As2[k*33+tr+16];
            float4 bf = *(const float4*)&Bs[k*68 + tc*4];
            ull b0 = ((const ull*)&bf)[0], b1 = ((const ull*)&bf)[1];
            acc[0][0]=ffma2(a0,b0,acc[0][0]); acc[0][1]=ffma2(a0,b1,acc[0][1]);
            acc[1][0]=ffma2(a1,b0,acc[1][0]); acc[1][1]=ffma2(a1,b1,acc[1][1]);
        }
        __syncthreads();
    }
    float* P = g_part + (size_t)blockIdx.z*MN;
    #pragma unroll
    for (int rr=0; rr<2; rr++){
        int gm = m0 + tr + rr*16;
        if (gm < MD){
            ull* cp = (ull*)(P + gm*HD + n0 + tc*4);
            cp[0] = acc[rr][0]; cp[1] = acc[rr][1];
        }
    }
}

// sum S slices per job (float4)
__global__ void k_red(int S, int njobs, int d0, int d1, int d2, int d3){
    int i4 = blockIdx.x*256 + threadIdx.x;
    if (i4 >= njobs*12800) return;
    int job = i4 / 12800, e4 = i4 - job*12800;
    const float4* P = (const float4*)g_part;
    float4 s = make_float4(0.f,0.f,0.f,0.f);
    for (int z=0; z<S; z++){
        float4 v = P[(size_t)(job*S+z)*12800 + e4];
        s.x+=v.x; s.y+=v.y; s.z+=v.z; s.w+=v.w;
    }
    int dc = (job==0)?d0:(job==1)?d1:(job==2)?d2:d3;
    ((float4*)sel_buf(dc))[e4] = s;
}

// reduce for h with bias+relu (float4). grid 50.
__global__ void k_redh(int S, const float* __restrict__ bias){
    int i4 = blockIdx.x*256 + threadIdx.x;
    const float4* P = (const float4*)g_part;
    float4 s = make_float4(0.f,0.f,0.f,0.f);
    for (int z=0; z<S; z++){
        float4 v = P[(size_t)z*12800 + i4];
        s.x+=v.x; s.y+=v.y; s.z+=v.z; s.w+=v.w;
    }
    float4 b = ((const float4*)bias)[i4 & 127];
    s.x = fmaxf(s.x+b.x,0.f); s.y = fmaxf(s.y+b.y,0.f);
    s.z = fmaxf(s.z+b.z,0.f); s.w = fmaxf(s.w+b.w,0.f);
    ((float4*)g_h)[i4] = s;
}

// ---------------- edge logits + pair compaction. grid (100,13), 256 thr ----------------
__global__ void k_el(const float* __restrict__ bel, const float* __restrict__ Wee,
                     const float* __restrict__ bee, float* __restrict__ out_lg){
    __shared__ float sWee[4*HD];
    __shared__ float sbel[HD];
    const int t = threadIdx.x;
    #pragma unroll
    for (int q=0; q<8; q++) sWee[t + q*256] = Wee[t + q*256];
    sbel[t] = bel[t]; sbel[t+256] = bel[t+256];
    __syncthreads();
    const int i = blockIdx.x;
    const int w = t >> 5, lane = t & 31;
    const int j = blockIdx.y*8 + w;
    if (j >= MD) return;
    const float* Ar = g_A + i*HD;
    const float* Br = g_B + j*HD;
    float p0=0.f, p1=0.f, p2=0.f, p3=0.f;
    #pragma unroll
    for (int s=0; s<16; s++){
        int h = lane + s*32;
        float v = fmaxf(Ar[h] + Br[h] + sbel[h], 0.f);
        p0 += v*sWee[h]; p1 += v*sWee[HD+h]; p2 += v*sWee[2*HD+h]; p3 += v*sWee[3*HD+h];
    }
    #pragma unroll
    for (int o=16; o; o>>=1){
        p0 += __shfl_xor_sync(~0u, p0, o);
        p1 += __shfl_xor_sync(~0u, p1, o);
        p2 += __shfl_xor_sync(~0u, p2, o);
        p3 += __shfl_xor_sync(~0u, p3, o);
    }
    if (lane == 0){
        p0 += bee[0]; p1 += bee[1]; p2 += bee[2]; p3 += bee[3];
        int p = i*MD + j;
        *(float4*)(out_lg + p*4) = make_float4(p0, p1, p2, p3);
        if (g_nodeok[i] && g_nodeok[j] && (p0>0.f || p1>0.f || p2>0.f || p3>0.f)){
            int pos = atomicAdd(&g_paircnt, 1);
            g_pairlist[pos] = p;
        }
    }
}

// ---------------- gathered edge GEMM, both iters, wavefront-lean A path ----------------
// grid (8,157), 256 thr. A in smem as f32, 4 consecutive rows/thread -> 1 broadcast LDS.128.
// Double-buffered, one sync per 16-k tile, LDG prefetch distance 2.
__global__ void k_ce(const float* __restrict__ We0, const float* __restrict__ We1,
                     const float* __restrict__ bel){
    __shared__ int   pp[64], pi[64], pj[64];
    __shared__ float sbel[HD];
    __shared__ float As [2][16*68];
    __shared__ float Bs0[2][16*68];
    __shared__ float Bs1[2][16*68];
    const int cnt = g_paircnt;
    const int m0  = blockIdx.y*64;
    if (m0 >= cnt) return;
    const int n0 = blockIdx.x*64;
    const int t = threadIdx.x;
    if (t < 64){
        int p = (m0 + t < cnt) ? g_pairlist[m0 + t] : g_pairlist[m0];
        pp[t] = p; pi[t] = (p/MD)*HD; pj[t] = (p%MD)*HD;
    }
    sbel[t] = bel[t]; sbel[t+256] = bel[t+256];
    __syncthreads();
    const int tr = t>>4, tc = t&15;
    // loaders: each thread owns column r (A-row / B-col) and 4 k values
    const int lr  = t & 63;           // row/col 0..63
    const int lk4 = (t >> 6) * 4;     // k offset within tile: 0,4,8,12
    const int piR = pi[lr], pjR = pj[lr];
    float va[4], vb[4], w0[4], w1[4];
    // prologue: LDG tile 0
    #pragma unroll
    for (int q=0; q<4; q++){
        va[q] = g_A[piR + lk4 + q];
        vb[q] = g_B[pjR + lk4 + q];
        w0[q] = We0[(lk4 + q)*HD + n0 + lr];
        w1[q] = We1[(lk4 + q)*HD + n0 + lr];
    }
    // STS tile 0 -> buf 0
    #pragma unroll
    for (int q=0; q<4; q++){
        int kk = lk4 + q;
        As [0][kk*68 + lr] = fmaxf(va[q] + vb[q] + sbel[kk], 0.f);
        Bs0[0][kk*68 + lr] = w0[q];
        Bs1[0][kk*68 + lr] = w1[q];
    }
    __syncthreads();
    // LDG tile 1
    #pragma unroll
    for (int q=0; q<4; q++){
        va[q] = g_A[piR + 16 + lk4 + q];
        vb[q] = g_B[pjR + 16 + lk4 + q];
        w0[q] = We0[(16 + lk4 + q)*HD + n0 + lr];
        w1[q] = We1[(16 + lk4 + q)*HD + n0 + lr];
    }
    ull acc0[4][2] = {}, acc1[4][2] = {};
    for (int kt=0; kt<32; kt++){
        const int c = kt & 1;
        if (kt+1 < 32){
            int ko = (kt+1)*16;
            #pragma unroll
            for (int q=0; q<4; q++){
                int kk = lk4 + q;
                As [c^1][kk*68 + lr] = fmaxf(va[q] + vb[q] + sbel[ko + kk], 0.f);
                Bs0[c^1][kk*68 + lr] = w0[q];
                Bs1[c^1][kk*68 + lr] = w1[q];
            }
        }
        if (kt+2 < 32){
            int ko = (kt+2)*16;
            #pragma unroll
            for (int q=0; q<4; q++){
                va[q] = g_A[piR + ko + lk4 + q];
                vb[q] = g_B[pjR + ko + lk4 + q];
                w0[q] = We0[(ko + lk4 + q)*HD + n0 + lr];
                w1[q] = We1[(ko + lk4 + q)*HD + n0 + lr];
            }
        }
        #pragma unroll
        for (int k=0; k<16; k++){
            float4 af = *(const float4*)&As[c][k*68 + tr*4];   // 4 consecutive rows, broadcast
            ull a0 = dup2(af.x), a1 = dup2(af.y), a2 = dup2(af.z), a3 = dup2(af.w);
            float4 b0f = *(const float4*)&Bs0[c][k*68 + tc*4];
            float4 b1f = *(const float4*)&Bs1[c][k*68 + tc*4];
            ull p0 = ((const ull*)&b0f)[0], p1 = ((const ull*)&b0f)[1];
            ull q0 = ((const ull*)&b1f)[0], q1 = ((const ull*)&b1f)[1];
            acc0[0][0]=ffma2(a0,p0,acc0[0][0]); acc0[0][1]=ffma2(a0,p1,acc0[0][1]);
            acc0[1][0]=ffma2(a1,p0,acc0[1][0]); acc0[1][1]=ffma2(a1,p1,acc0[1][1]);
            acc0[2][0]=ffma2(a2,p0,acc0[2][0]); acc0[2][1]=ffma2(a2,p1,acc0[2][1]);
            acc0[3][0]=ffma2(a3,p0,acc0[3][0]); acc0[3][1]=ffma2(a3,p1,acc0[3][1]);
            acc1[0][0]=ffma2(a0,q0,acc1[0][0]); acc1[0][1]=ffma2(a0,q1,acc1[0][1]);
            acc1[1][0]=ffma2(a1,q0,acc1[1][0]); acc1[1][1]=ffma2(a1,q1,acc1[1][1]);
            acc1[2][0]=ffma2(a2,q0,acc1[2][0]); acc1[2][1]=ffma2(a2,q1,acc1[2][1]);
            acc1[3][0]=ffma2(a3,q0,acc1[3][0]); acc1[3][1]=ffma2(a3,q1,acc1[3][1]);
        }
        __syncthreads();
    }
    #pragma unroll
    for (int i=0; i<4; i++){
        int rl = tr*4 + i;                 // rows are consecutive per thread now
        if (m0 + rl < cnt){
            int off = pp[rl]*HD + n0 + tc*4;
            ull* c0 = (ull*)(g_Ce0 + off);
            c0[0] = acc0[i][0]; c0[1] = acc0[i][1];
            ull* c1 = (ull*)(g_Ce1 + off);
            c1[0] = acc1[i][0]; c1[1] = acc1[i][1];
        }
    }
}

// ---------------- message pass + scatter-sum. grid 100, 512 thr, 2-deep prefetch ----------------
__global__ void k_msg(int it, const float* __restrict__ lgg,
                      const float* __restrict__ Wt, const float* __restrict__ bne){
    __shared__ float lg[400];
    __shared__ int   jl[100];
    __shared__ int   njl;
    const float* childin  = it ? g_child1 : g_child0;
    float*       childout = it ? g_child2 : g_child1;
    const float* Ce       = it ? g_Ce1    : g_Ce0;
    const int i = blockIdx.x, h = threadIdx.x;
    if (h < 400) lg[h] = lgg[i*400 + h];
    __syncthreads();
    if (h == 0){
        int n = 0;
        if (g_nodeok[i]){
            for (int j=0; j<MD; j++){
                if (!g_nodeok[j]) continue;
                if (lg[j*4]>0.f || lg[j*4+1]>0.f || lg[j*4+2]>0.f || lg[j*4+3]>0.f) jl[n++] = j;
            }
        }
        njl = n;
    }
    __syncthreads();
    float cin = childin[i*HD + h];
    bool any = (g_paircnt > 0);
    float acc = 0.f;
    const int n = njl;
    float base_i = g_Ai[i*HD + h] + bne[h];
    float wt0 = Wt[h], wt1 = Wt[HD+h], wt2 = Wt[2*HD+h], wt3 = Wt[3*HD+h];
    const float* CeI = Ce + (long long)i*MD*HD;
    float bA=0.f, cA=0.f, bB=0.f, cB=0.f;
    if (n > 0){ int j0 = jl[0]; bA = g_Bj[j0*HD+h]; cA = CeI[j0*HD+h]; }
    if (n > 1){ int j1 = jl[1]; bB = g_Bj[j1*HD+h]; cB = CeI[j1*HD+h]; }
    for (int q=0; q<n; q++){
        int j = jl[q];
        float cb = bA, cc = cA;
        bA = bB; cA = cB;
        if (q+2 < n){
            int jn = jl[q+2];
            bB = g_Bj[jn*HD + h]; cB = CeI[jn*HD + h];
        }
        float l0 = lg[j*4], l1 = lg[j*4+1], l2 = lg[j*4+2], l3 = lg[j*4+3];
        float base = base_i + cb + cc;
        if (l0 > 0.f) acc += fmaxf(fmaf(l0, wt0, base), 0.f);
        if (l1 > 0.f) acc += fmaxf(fmaf(l1, wt1, base), 0.f);
        if (l2 > 0.f) acc += fmaxf(fmaf(l2, wt2, base), 0.f);
        if (l3 > 0.f) acc += fmaxf(fmaf(l3, wt3, base), 0.f);
    }
    childout[i*HD + h] = any ? acc : cin;
}

// ---------------- heads partials: x<8 child2 (N=512), x==8 sem (N=57). grid (9,4,4) ----------------
__global__ void k_heads(const float* __restrict__ Wc2, const float* __restrict__ Ws){
    __shared__ ull   As2[16*33];
    __shared__ float Bs[16*68];
    const bool semjob = (blockIdx.x == 8);
    const float* B = semjob ? Ws : Wc2;
    const int N   = semjob ? 57 : 512;
    const int n0  = semjob ? 0  : blockIdx.x*64;
    const int m0  = blockIdx.y*32;
    const int kb  = blockIdx.z*128;
    const int t = threadIdx.x, tr = t>>4, tc = t&15;
    const int ar0 = t>>4, ak = t&15, ar1 = ar0+16;
    const int bn = t&63, bk0 = t>>6;
    const int gm0 = m0+ar0, gm1 = m0+ar1;
    const bool bok = (n0 + bn) < N;
    float pa0, pa1, pb0, pb1, pb2, pb3;
    {
        int k = kb + ak;
        pa0 = (gm0 < MD) ? g_h[gm0*HD + k] : 0.f;
        pa1 = (gm1 < MD) ? g_h[gm1*HD + k] : 0.f;
        int kB = kb + bk0;
        pb0 = bok ? B[(kB   )*N + n0+bn] : 0.f;
        pb1 = bok ? B[(kB+4 )*N + n0+bn] : 0.f;
        pb2 = bok ? B[(kB+8 )*N + n0+bn] : 0.f;
        pb3 = bok ? B[(kB+12)*N + n0+bn] : 0.f;
    }
    ull acc[2][2] = {};
    for (int kt=0; kt<8; kt++){
        As2[ak*33 + ar0] = dup2(pa0);
        As2[ak*33 + ar1] = dup2(pa1);
        Bs[(bk0   )*68 + bn] = pb0;
        Bs[(bk0+4 )*68 + bn] = pb1;
        Bs[(bk0+8 )*68 + bn] = pb2;
        Bs[(bk0+12)*68 + bn] = pb3;
        __syncthreads();
        if (kt+1 < 8){
            int k = kb + (kt+1)*16 + ak;
            pa0 = (gm0 < MD) ? g_h[gm0*HD + k] : 0.f;
            pa1 = (gm1 < MD) ? g_h[gm1*HD + k] : 0.f;
            int kB = kb + (kt+1)*16 + bk0;
            pb0 = bok ? B[(kB   )*N + n0+bn] : 0.f;
            pb1 = bok ? B[(kB+4 )*N + n0+bn] : 0.f;
            pb2 = bok ? B[(kB+8 )*N + n0+bn] : 0.f;
            pb3 = bok ? B[(kB+12)*N + n0+bn] : 0.f;
        }
        #pragma unroll
        for (int k=0; k<16; k++){
            ull a0 = As2[k*33+tr], a1 = As2[k*33+tr+16];
            float4 bf = *(const float4*)&Bs[k*68 + tc*4];
            ull b0 = ((const ull*)&bf)[0], b1 = ((const ull*)&bf)[1];
            acc[0][0]=ffma2(a0,b0,acc[0][0]); acc[0][1]=ffma2(a0,b1,acc[0][1]);
            acc[1][0]=ffma2(a1,b0,acc[1][0]); acc[1][1]=ffma2(a1,b1,acc[1][1]);
        }
        __syncthreads();
    }
    const int sl = blockIdx.z;
    #pragma unroll
    for (int rr=0; rr<2; rr++){
        int gm = m0 + tr + rr*16;
        if (gm >= MD) continue;
        float r0 = __uint_as_float((unsigned)(acc[rr][0]      ));
        float r1 = __uint_as_float((unsigned)(acc[rr][0] >> 32));
        float r2 = __uint_as_float((unsigned)(acc[rr][1]      ));
        float r3 = __uint_as_float((unsigned)(acc[rr][1] >> 32));
        int gn = n0 + tc*4;
        if (!semjob){
            ull* cp = (ull*)(g_part + (size_t)sl*MN + gm*HD + gn);
            cp[0] = acc[rr][0]; cp[1] = acc[rr][1];
        } else {
            float* P = g_partS + sl*5700 + gm*57;
            if (gn   < 57) P[gn  ] = r0;
            if (gn+1 < 57) P[gn+1] = r1;
            if (gn+2 < 57) P[gn+2] = r2;
            if (gn+3 < 57) P[gn+3] = r3;
        }
    }
}

// final output reduce. blocks 0..49: child_out float4, 50..72: sem scalar.
__global__ void k_out(const float* __restrict__ bc2, const float* __restrict__ bs,
                      float* __restrict__ out_co, float* __restrict__ out_sem){
    if (blockIdx.x < 50){
        int i4 = blockIdx.x*256 + threadIdx.x;
        const float4* P = (const float4*)g_part;
        float4 s = make_float4(0.f,0.f,0.f,0.f);
        #pragma unroll
        for (int z=0; z<4; z++){
            float4 v = P[(size_t)z*12800 + i4];
            s.x+=v.x; s.y+=v.y; s.z+=v.z; s.w+=v.w;
        }
        float4 b = ((const float4*)bc2)[i4 & 127];
        s.x = fmaxf(s.x+b.x,0.f); s.y = fmaxf(s.y+b.y,0.f);
        s.z = fmaxf(s.z+b.z,0.f); s.w = fmaxf(s.w+b.w,0.f);
        ((float4*)out_co)[i4] = s;
    } else {
        int e = (blockIdx.x-50)*256 + threadIdx.x;
        if (e >= 5700) return;
        float s = 0.f;
        #pragma unroll
        for (int z=0; z<4; z++) s += g_partS[z*5700 + e];
        out_sem[e] = s + bs[e % 57];
    }
}

// ---------------- launch ----------------
extern "C" void kernel_launch(void* const* d_in, const int* in_sizes, int n_in,
                              void* d_out, int out_size){
    const float* pf  = (const float*)d_in[0];
    const float* Wp  = (const float*)d_in[1];
    const float* bp  = (const float*)d_in[2];
    const float* Wx  = (const float*)d_in[3];
    const float* bx  = (const float*)d_in[4];
    const float* Wel = (const float*)d_in[5];
    const float* bel = (const float*)d_in[6];
    const float* Wee = (const float*)d_in[7];
    const float* bee = (const float*)d_in[8];
    const float* Wne = (const float*)d_in[9];
    const float* bne = (const float*)d_in[10];
    const float* Wc  = (const float*)d_in[11];
    const float* bc  = (const float*)d_in[12];
    const float* Ws  = (const float*)d_in[13];
    const float* bs  = (const float*)d_in[14];
    const float* Wc2 = (const float*)d_in[15];
    const float* bc2 = (const float*)d_in[16];

    float* out     = (float*)d_out;
    float* out_co  = out;
    float* out_sem = out + 51200;
    float* out_ex  = out + 56900;
    float* out_lg  = out + 57000;

    k_gemv_part<<<dim3(50,4),256>>>(pf, Wp);
    k_gemv_fin<<<100,128>>>(bp, Wx, bx, out_ex);
    k_gp<<<dim3(8,4,16),256>>>(5 | (5<<8) | (5<<16) | (5<<24), 512, 4,
                               Wel, Wel + 512*512, Wne, Wne + 512*512);
    k_red<<<200,256>>>(4, 4, 0, 1, 2, 3);
    k_el<<<dim3(100,13),256>>>(bel, Wee, bee, out_lg);
    k_ce<<<dim3(8,157),256>>>(Wne + 1024*512, Wne + (1540+1024)*512, bel);
    k_msg<<<100,512>>>(0, out_lg, Wne + 1536*512, bne);
    k_gp<<<dim3(8,4,8),256>>>(6 | (6<<8), 512, 4,
                              Wne + 1540*512, Wne + (1540+512)*512, Wne, Wne);
    k_red<<<100,256>>>(4, 2, 2, 3, 0, 0);
    k_msg<<<100,512>>>(1, out_lg, Wne + (1540+1536)*512, bne + 512);
    k_gp<<<dim3(8,4,8),256>>>(9, 1536, 8, Wc, Wc, Wc, Wc);
    k_redh<<<50,256>>>(8, bc);
    k_heads<<<dim3(9,4,4),256>>>(Wc2, Ws);
    k_out<<<73,256>>>(bc2, bs, out_co, out_sem);
}

// round 11
// speedup vs baseline: 1.4990x; 1.4990x over previous
#include <cuda_runtime.h>

typedef unsigned long long ull;

#define MD 100
#define HD 512
#define NP 10000
#define MN 51200

// ---------------- device scratch ----------------
__device__ __align__(16) float g_child0[MD*HD];
__device__ __align__(16) float g_child1[MD*HD];
__device__ __align__(16) float g_child2[MD*HD];
__device__ __align__(16) float g_A[MD*HD];
__device__ __align__(16) float g_B[MD*HD];
__device__ __align__(16) float g_Ai[MD*HD];
__device__ __align__(16) float g_Bj[MD*HD];
__device__ __align__(16) float g_h[MD*HD];
__device__ __align__(16) float g_Ce0[NP*HD];
__device__ __align__(16) float g_Ce1[NP*HD];
__device__ __align__(16) float g_gpart[4*MN];
__device__ __align__(16) float g_part[16*MN];
__device__ __align__(16) float g_partS[4*5700];
__device__ int   g_nodeok[MD];
__device__ int   g_pairlist[NP];
__device__ int   g_paircnt;

__device__ __forceinline__ ull ffma2(ull a, ull b, ull c){
    ull d;
    asm("fma.rn.f32x2 %0, %1, %2, %3;" : "=l"(d) : "l"(a), "l"(b), "l"(c));
    return d;
}
__device__ __forceinline__ ull dup2(float v){
    unsigned u = __float_as_uint(v);
    return ((ull)u << 32) | (ull)u;
}
__device__ __forceinline__ float* sel_buf(int code){
    switch (code){
        case 0: return g_A;      case 1: return g_B;
        case 2: return g_Ai;     case 3: return g_Bj;
        case 4: return g_h;      case 5: return g_child0;
        case 6: return g_child1; default: return g_child2;
    }
}
__device__ __forceinline__ float fetchA(int code, int m, int k){
    if (code == 9){   // virtual concat [child0|child1|child2]
        int q = k >> 9, kk = k & 511;
        const float* s = (q==0) ? g_child0 : (q==1) ? g_child1 : g_child2;
        return s[m*HD + kk];
    }
    return sel_buf(code)[m*HD + k];
}

// ---------------- parent GEMV: float4, split-K. grid (50,4), 256 thr ----------------
__global__ void k_gemv_part(const float* __restrict__ pf, const float* __restrict__ Wp){
    __shared__ float pfs[128];
    const int z = blockIdx.y;
    const int c4 = blockIdx.x*256 + threadIdx.x;
    if (threadIdx.x < 128) pfs[threadIdx.x] = pf[z*128 + threadIdx.x];
    __syncthreads();
    const float4* w = (const float4*)Wp + (long long)(z*128)*12800 + c4;
    float4 a = make_float4(0.f,0.f,0.f,0.f);
    #pragma unroll 8
    for (int k=0; k<128; k++){
        float4 wv = w[(long long)k*12800];
        float s = pfs[k];
        a.x += s*wv.x; a.y += s*wv.y; a.z += s*wv.z; a.w += s*wv.w;
    }
    ((float4*)g_gpart)[z*12800 + c4] = a;
}

// finisher + exists logits fused. grid 100, 128 thr.
__global__ void k_gemv_fin(const float* __restrict__ bp, const float* __restrict__ Wx,
                           const float* __restrict__ bx, float* __restrict__ out_ex){
    __shared__ float red[4];
    const int m = blockIdx.x, t = threadIdx.x;
    const int c4 = m*128 + t;
    const float4* gp = (const float4*)g_gpart;
    float4 s0 = gp[c4], s1 = gp[12800+c4], s2 = gp[2*12800+c4], s3 = gp[3*12800+c4];
    float4 b  = ((const float4*)bp)[c4];
    float4 v;
    v.x = fmaxf(s0.x+s1.x+s2.x+s3.x+b.x, 0.f);
    v.y = fmaxf(s0.y+s1.y+s2.y+s3.y+b.y, 0.f);
    v.z = fmaxf(s0.z+s1.z+s2.z+s3.z+b.z, 0.f);
    v.w = fmaxf(s0.w+s1.w+s2.w+s3.w+b.w, 0.f);
    ((float4*)g_child0)[c4] = v;
    float4 wx = ((const float4*)Wx)[t];
    float p = v.x*wx.x + v.y*wx.y + v.z*wx.z + v.w*wx.w;
    #pragma unroll
    for (int o=16; o; o>>=1) p += __shfl_xor_sync(~0u, p, o);
    if ((t & 31) == 0) red[t>>5] = p;
    __syncthreads();
    if (t == 0){
        float vv = red[0]+red[1]+red[2]+red[3] + bx[0];
        out_ex[m]   = vv;
        g_nodeok[m] = (vv > 0.f) ? 1 : 0;
        if (m == 0) g_paircnt = 0;
    }
}

// ---------------- split-K multi-job GEMM partials, pipelined ----------------
__global__ void k_gp(int acodes, int Klen, int KS,
                     const float* __restrict__ B0, const float* __restrict__ B1,
                     const float* __restrict__ B2, const float* __restrict__ B3){
    __shared__ ull   As2[16*33];
    __shared__ float Bs[16*68];
    const int KSL = Klen / KS;
    const int job = blockIdx.z / KS, sl = blockIdx.z % KS;
    const int Acode = (acodes >> (8*job)) & 255;
    const float* B = (job==0)?B0:(job==1)?B1:(job==2)?B2:B3;
    const int kb = sl*KSL;
    const int n0 = blockIdx.x*64, m0 = blockIdx.y*32;
    const int t = threadIdx.x, tr = t>>4, tc = t&15;
    const int ar0 = t>>4, ak = t&15, ar1 = ar0+16;
    const int bn = t&63, bk0 = t>>6;
    const int gm0 = m0+ar0, gm1 = m0+ar1;
    float pa0, pa1, pb0, pb1, pb2, pb3;
    {
        int k = kb + ak;
        pa0 = (gm0 < MD) ? fetchA(Acode, gm0, k) : 0.f;
        pa1 = (gm1 < MD) ? fetchA(Acode, gm1, k) : 0.f;
        int kB = kb + bk0;
        pb0 = B[(kB   )*HD + n0+bn]; pb1 = B[(kB+4 )*HD + n0+bn];
        pb2 = B[(kB+8 )*HD + n0+bn]; pb3 = B[(kB+12)*HD + n0+bn];
    }
    ull acc[2][2] = {};
    const int nkt = KSL/16;
    for (int kt=0; kt<nkt; kt++){
        As2[ak*33 + ar0] = dup2(pa0);
        As2[ak*33 + ar1] = dup2(pa1);
        Bs[(bk0   )*68 + bn] = pb0;
        Bs[(bk0+4 )*68 + bn] = pb1;
        Bs[(bk0+8 )*68 + bn] = pb2;
        Bs[(bk0+12)*68 + bn] = pb3;
        __syncthreads();
        if (kt+1 < nkt){
            int k = kb + (kt+1)*16 + ak;
            pa0 = (gm0 < MD) ? fetchA(Acode, gm0, k) : 0.f;
            pa1 = (gm1 < MD) ? fetchA(Acode, gm1, k) : 0.f;
            int kB = kb + (kt+1)*16 + bk0;
            pb0 = B[(kB   )*HD + n0+bn]; pb1 = B[(kB+4 )*HD + n0+bn];
            pb2 = B[(kB+8 )*HD + n0+bn]; pb3 = B[(kB+12)*HD + n0+bn];
        }
        #pragma unroll
        for (int k=0; k<16; k++){
            ull a0 = As2[k*33+tr], a1 = As2[k*33+tr+16];
            float4 bf = *(const float4*)&Bs[k*68 + tc*4];
            ull b0 = ((const ull*)&bf)[0], b1 = ((const ull*)&bf)[1];
            acc[0][0]=ffma2(a0,b0,acc[0][0]); acc[0][1]=ffma2(a0,b1,acc[0][1]);
            acc[1][0]=ffma2(a1,b0,acc[1][0]); acc[1][1]=ffma2(a1,b1,acc[1][1]);
        }
        __syncthreads();
    }
    float* P = g_part + (size_t)blockIdx.z*MN;
    #pragma unroll
    for (int rr=0; rr<2; rr++){
        int gm = m0 + tr + rr*16;
        if (gm < MD){
            ull* cp = (ull*)(P + gm*HD + n0 + tc*4);
            cp[0] = acc[rr][0]; cp[1] = acc[rr][1];
        }
    }
}

// sum S slices per job (float4)
__global__ void k_red(int S, int njobs, int d0, int d1, int d2, int d3){
    int i4 = blockIdx.x*256 + threadIdx.x;
    if (i4 >= njobs*12800) return;
    int job = i4 / 12800, e4 = i4 - job*12800;
    const float4* P = (const float4*)g_part;
    float4 s = make_float4(0.f,0.f,0.f,0.f);
    for (int z=0; z<S; z++){
        float4 v = P[(size_t)(job*S+z)*12800 + e4];
        s.x+=v.x; s.y+=v.y; s.z+=v.z; s.w+=v.w;
    }
    int dc = (job==0)?d0:(job==1)?d1:(job==2)?d2:d3;
    ((float4*)sel_buf(dc))[e4] = s;
}

// reduce for h with bias+relu (float4). grid 50.
__global__ void k_redh(int S, const float* __restrict__ bias){
    int i4 = blockIdx.x*256 + threadIdx.x;
    const float4* P = (const float4*)g_part;
    float4 s = make_float4(0.f,0.f,0.f,0.f);
    for (int z=0; z<S; z++){
        float4 v = P[(size_t)z*12800 + i4];
        s.x+=v.x; s.y+=v.y; s.z+=v.z; s.w+=v.w;
    }
    float4 b = ((const float4*)bias)[i4 & 127];
    s.x = fmaxf(s.x+b.x,0.f); s.y = fmaxf(s.y+b.y,0.f);
    s.z = fmaxf(s.z+b.z,0.f); s.w = fmaxf(s.w+b.w,0.f);
    ((float4*)g_h)[i4] = s;
}

// ---------------- edge logits + pair compaction. grid (100,13), 256 thr ----------------
__global__ void k_el(const float* __restrict__ bel, const float* __restrict__ Wee,
                     const float* __restrict__ bee, float* __restrict__ out_lg){
    __shared__ float sWee[4*HD];
    __shared__ float sbel[HD];
    const int t = threadIdx.x;
    #pragma unroll
    for (int q=0; q<8; q++) sWee[t + q*256] = Wee[t + q*256];
    sbel[t] = bel[t]; sbel[t+256] = bel[t+256];
    __syncthreads();
    const int i = blockIdx.x;
    const int w = t >> 5, lane = t & 31;
    const int j = blockIdx.y*8 + w;
    if (j >= MD) return;
    const float* Ar = g_A + i*HD;
    const float* Br = g_B + j*HD;
    float p0=0.f, p1=0.f, p2=0.f, p3=0.f;
    #pragma unroll
    for (int s=0; s<16; s++){
        int h = lane + s*32;
        float v = fmaxf(Ar[h] + Br[h] + sbel[h], 0.f);
        p0 += v*sWee[h]; p1 += v*sWee[HD+h]; p2 += v*sWee[2*HD+h]; p3 += v*sWee[3*HD+h];
    }
    #pragma unroll
    for (int o=16; o; o>>=1){
        p0 += __shfl_xor_sync(~0u, p0, o);
        p1 += __shfl_xor_sync(~0u, p1, o);
        p2 += __shfl_xor_sync(~0u, p2, o);
        p3 += __shfl_xor_sync(~0u, p3, o);
    }
    if (lane == 0){
        p0 += bee[0]; p1 += bee[1]; p2 += bee[2]; p3 += bee[3];
        int p = i*MD + j;
        *(float4*)(out_lg + p*4) = make_float4(p0, p1, p2, p3);
        if (g_nodeok[i] && g_nodeok[j] && (p0>0.f || p1>0.f || p2>0.f || p3>0.f)){
            int pos = atomicAdd(&g_paircnt, 1);
            g_pairlist[pos] = p;
        }
    }
}

// ---------------- gathered edge GEMM, BOTH iterations fused. grid (8,157), 256 thr ----------------
// A-smem: pre-duplicated ull, stride 66 (16B-aligned pairs). Each thread owns 4 CONSECUTIVE
// rows -> A-reads are 2 broadcast LDS.128 per k (was 4 LDS.64): A wavefronts halved.
__global__ void k_ce(const float* __restrict__ We0, const float* __restrict__ We1,
                     const float* __restrict__ bel){
    __shared__ int   pp[64], pi[64], pj[64];
    __shared__ float sbel[HD];
    __shared__ __align__(16) ull As2[16*66];
    __shared__ float Bs0[16*68];
    __shared__ float Bs1[16*68];
    const int cnt = g_paircnt;
    const int m0  = blockIdx.y*64;
    if (m0 >= cnt) return;
    const int n0 = blockIdx.x*64;
    const int t = threadIdx.x;
    if (t < 64){
        int p = (m0 + t < cnt) ? g_pairlist[m0 + t] : g_pairlist[m0];
        pp[t] = p; pi[t] = (p/MD)*HD; pj[t] = (p%MD)*HD;
    }
    sbel[t] = bel[t]; sbel[t+256] = bel[t+256];
    __syncthreads();
    const int tr = t>>4, tc = t&15;
    const int ar = t>>4, ak = t&15;     // A loader lane mapping (unchanged)
    const int bn = t&63, bk0 = t>>6;    // B loader lane mapping (unchanged)
    float va[4], vb[4], w0[4], w1[4];
    #pragma unroll
    for (int q=0; q<4; q++){
        int r = ar + 16*q;
        va[q] = g_A[pi[r] + ak];
        vb[q] = g_B[pj[r] + ak];
        int kk = bk0 + 4*q;
        w0[q] = We0[kk*HD + n0 + bn];
        w1[q] = We1[kk*HD + n0 + bn];
    }
    ull acc0[4][2] = {}, acc1[4][2] = {};
    for (int kt=0; kt<32; kt++){
        #pragma unroll
        for (int q=0; q<4; q++){
            int r = ar + 16*q;
            As2[ak*66 + r] = dup2(fmaxf(va[q] + vb[q] + sbel[kt*16 + ak], 0.f));
            int kk = bk0 + 4*q;
            Bs0[kk*68 + bn] = w0[q];
            Bs1[kk*68 + bn] = w1[q];
        }
        __syncthreads();
        if (kt+1 < 32){
            int ko = (kt+1)*16;
            #pragma unroll
            for (int q=0; q<4; q++){
                int r = ar + 16*q;
                va[q] = g_A[pi[r] + ko + ak];
                vb[q] = g_B[pj[r] + ko + ak];
                int kk = ko + bk0 + 4*q;
                w0[q] = We0[kk*HD + n0 + bn];
                w1[q] = We1[kk*HD + n0 + bn];
            }
        }
        #pragma unroll
        for (int k=0; k<16; k++){
            // rows 4*tr .. 4*tr+3 via two 16B broadcast loads
            ulonglong2 aa0 = *(const ulonglong2*)&As2[k*66 + tr*4];
            ulonglong2 aa1 = *(const ulonglong2*)&As2[k*66 + tr*4 + 2];
            ull a0 = aa0.x, a1 = aa0.y, a2 = aa1.x, a3 = aa1.y;
            float4 b0f = *(const float4*)&Bs0[k*68 + tc*4];
            float4 b1f = *(const float4*)&Bs1[k*68 + tc*4];
            ull p0 = ((const ull*)&b0f)[0], p1 = ((const ull*)&b0f)[1];
            ull q0 = ((const ull*)&b1f)[0], q1 = ((const ull*)&b1f)[1];
            acc0[0][0]=ffma2(a0,p0,acc0[0][0]); acc0[0][1]=ffma2(a0,p1,acc0[0][1]);
            acc0[1][0]=ffma2(a1,p0,acc0[1][0]); acc0[1][1]=ffma2(a1,p1,acc0[1][1]);
            acc0[2][0]=ffma2(a2,p0,acc0[2][0]); acc0[2][1]=ffma2(a2,p1,acc0[2][1]);
            acc0[3][0]=ffma2(a3,p0,acc0[3][0]); acc0[3][1]=ffma2(a3,p1,acc0[3][1]);
            acc1[0][0]=ffma2(a0,q0,acc1[0][0]); acc1[0][1]=ffma2(a0,q1,acc1[0][1]);
            acc1[1][0]=ffma2(a1,q0,acc1[1][0]); acc1[1][1]=ffma2(a1,q1,acc1[1][1]);
            acc1[2][0]=ffma2(a2,q0,acc1[2][0]); acc1[2][1]=ffma2(a2,q1,acc1[2][1]);
            acc1[3][0]=ffma2(a3,q0,acc1[3][0]); acc1[3][1]=ffma2(a3,q1,acc1[3][1]);
        }
        __syncthreads();
    }
    #pragma unroll
    for (int q=0; q<4; q++){
        int rl = tr*4 + q;                 // consecutive rows per thread
        if (m0 + rl < cnt){
            int off = pp[rl]*HD + n0 + tc*4;
            ull* c0 = (ull*)(g_Ce0 + off);
            c0[0] = acc0[q][0]; c0[1] = acc0[q][1];
            ull* c1 = (ull*)(g_Ce1 + off);
            c1[0] = acc1[q][0]; c1[1] = acc1[q][1];
        }
    }
}

// ---------------- message pass + scatter-sum. grid 100, 512 thr, 2-deep prefetch ----------------
__global__ void k_msg(int it, const float* __restrict__ lgg,
                      const float* __restrict__ Wt, const float* __restrict__ bne){
    __shared__ float lg[400];
    __shared__ int   jl[100];
    __shared__ int   njl;
    const float* childin  = it ? g_child1 : g_child0;
    float*       childout = it ? g_child2 : g_child1;
    const float* Ce       = it ? g_Ce1    : g_Ce0;
    const int i = blockIdx.x, h = threadIdx.x;
    if (h < 400) lg[h] = lgg[i*400 + h];
    __syncthreads();
    if (h == 0){
        int n = 0;
        if (g_nodeok[i]){
            for (int j=0; j<MD; j++){
                if (!g_nodeok[j]) continue;
                if (lg[j*4]>0.f || lg[j*4+1]>0.f || lg[j*4+2]>0.f || lg[j*4+3]>0.f) jl[n++] = j;
            }
        }
        njl = n;
    }
    __syncthreads();
    float cin = childin[i*HD + h];
    bool any = (g_paircnt > 0);
    float acc = 0.f;
    const int n = njl;
    float base_i = g_Ai[i*HD + h] + bne[h];
    float wt0 = Wt[h], wt1 = Wt[HD+h], wt2 = Wt[2*HD+h], wt3 = Wt[3*HD+h];
    const float* CeI = Ce + (long long)i*MD*HD;
    float bA=0.f, cA=0.f, bB=0.f, cB=0.f;
    if (n > 0){ int j0 = jl[0]; bA = g_Bj[j0*HD+h]; cA = CeI[j0*HD+h]; }
    if (n > 1){ int j1 = jl[1]; bB = g_Bj[j1*HD+h]; cB = CeI[j1*HD+h]; }
    for (int q=0; q<n; q++){
        int j = jl[q];
        float cb = bA, cc = cA;
        bA = bB; cA = cB;
        if (q+2 < n){
            int jn = jl[q+2];
            bB = g_Bj[jn*HD + h]; cB = CeI[jn*HD + h];
        }
        float l0 = lg[j*4], l1 = lg[j*4+1], l2 = lg[j*4+2], l3 = lg[j*4+3];
        float base = base_i + cb + cc;
        if (l0 > 0.f) acc += fmaxf(fmaf(l0, wt0, base), 0.f);
        if (l1 > 0.f) acc += fmaxf(fmaf(l1, wt1, base), 0.f);
        if (l2 > 0.f) acc += fmaxf(fmaf(l2, wt2, base), 0.f);
        if (l3 > 0.f) acc += fmaxf(fmaf(l3, wt3, base), 0.f);
    }
    childout[i*HD + h] = any ? acc : cin;
}

// ---------------- heads partials: x<8 child2 (N=512), x==8 sem (N=57). grid (9,4,4) ----------------
__global__ void k_heads(const float* __restrict__ Wc2, const float* __restrict__ Ws){
    __shared__ ull   As2[16*33];
    __shared__ float Bs[16*68];
    const bool semjob = (blockIdx.x == 8);
    const float* B = semjob ? Ws : Wc2;
    const int N   = semjob ? 57 : 512;
    const int n0  = semjob ? 0  : blockIdx.x*64;
    const int m0  = blockIdx.y*32;
    const int kb  = blockIdx.z*128;
    const int t = threadIdx.x, tr = t>>4, tc = t&15;
    const int ar0 = t>>4, ak = t&15, ar1 = ar0+16;
    const int bn = t&63, bk0 = t>>6;
    const int gm0 = m0+ar0, gm1 = m0+ar1;
    const bool bok = (n0 + bn) < N;
    float pa0, pa1, pb0, pb1, pb2, pb3;
    {
        int k = kb + ak;
        pa0 = (gm0 < MD) ? g_h[gm0*HD + k] : 0.f;
        pa1 = (gm1 < MD) ? g_h[gm1*HD + k] : 0.f;
        int kB = kb + bk0;
        pb0 = bok ? B[(kB   )*N + n0+bn] : 0.f;
        pb1 = bok ? B[(kB+4 )*N + n0+bn] : 0.f;
        pb2 = bok ? B[(kB+8 )*N + n0+bn] : 0.f;
        pb3 = bok ? B[(kB+12)*N + n0+bn] : 0.f;
    }
    ull acc[2][2] = {};
    for (int kt=0; kt<8; kt++){
        As2[ak*33 + ar0] = dup2(pa0);
        As2[ak*33 + ar1] = dup2(pa1);
        Bs[(bk0   )*68 + bn] = pb0;
        Bs[(bk0+4 )*68 + bn] = pb1;
        Bs[(bk0+8 )*68 + bn] = pb2;
        Bs[(bk0+12)*68 + bn] = pb3;
        __syncthreads();
        if (kt+1 < 8){
            int k = kb + (kt+1)*16 + ak;
            pa0 = (gm0 < MD) ? g_h[gm0*HD + k] : 0.f;
            pa1 = (gm1 < MD) ? g_h[gm1*HD + k] : 0.f;
            int kB = kb + (kt+1)*16 + bk0;
            pb0 = bok ? B[(kB   )*N + n0+bn] : 0.f;
            pb1 = bok ? B[(kB+4 )*N + n0+bn] : 0.f;
            pb2 = bok ? B[(kB+8 )*N + n0+bn] : 0.f;
            pb3 = bok ? B[(kB+12)*N + n0+bn] : 0.f;
        }
        #pragma unroll
        for (int k=0; k<16; k++){
            ull a0 = As2[k*33+tr], a1 = As2[k*33+tr+16];
            float4 bf = *(const float4*)&Bs[k*68 + tc*4];
            ull b0 = ((const ull*)&bf)[0], b1 = ((const ull*)&bf)[1];
            acc[0][0]=ffma2(a0,b0,acc[0][0]); acc[0][1]=ffma2(a0,b1,acc[0][1]);
            acc[1][0]=ffma2(a1,b0,acc[1][0]); acc[1][1]=ffma2(a1,b1,acc[1][1]);
        }
        __syncthreads();
    }
    const int sl = blockIdx.z;
    #pragma unroll
    for (int rr=0; rr<2; rr++){
        int gm = m0 + tr + rr*16;
        if (gm >= MD) continue;
        float r0 = __uint_as_float((unsigned)(acc[rr][0]      ));
        float r1 = __uint_as_float((unsigned)(acc[rr][0] >> 32));
        float r2 = __uint_as_float((unsigned)(acc[rr][1]      ));
        float r3 = __uint_as_float((unsigned)(acc[rr][1] >> 32));
        int gn = n0 + tc*4;
        if (!semjob){
            ull* cp = (ull*)(g_part + (size_t)sl*MN + gm*HD + gn);
            cp[0] = acc[rr][0]; cp[1] = acc[rr][1];
        } else {
            float* P = g_partS + sl*5700 + gm*57;
            if (gn   < 57) P[gn  ] = r0;
            if (gn+1 < 57) P[gn+1] = r1;
            if (gn+2 < 57) P[gn+2] = r2;
            if (gn+3 < 57) P[gn+3] = r3;
        }
    }
}

// final output reduce. blocks 0..49: child_out float4, 50..72: sem scalar.
__global__ void k_out(const float* __restrict__ bc2, const float* __restrict__ bs,
                      float* __restrict__ out_co, float* __restrict__ out_sem){
    if (blockIdx.x < 50){
        int i4 = blockIdx.x*256 + threadIdx.x;
        const float4* P = (const float4*)g_part;
        float4 s = make_float4(0.f,0.f,0.f,0.f);
        #pragma unroll
        for (int z=0; z<4; z++){
            float4 v = P[(size_t)z*12800 + i4];
            s.x+=v.x; s.y+=v.y; s.z+=v.z; s.w+=v.w;
        }
        float4 b = ((const float4*)bc2)[i4 & 127];
        s.x = fmaxf(s.x+b.x,0.f); s.y = fmaxf(s.y+b.y,0.f);
        s.z = fmaxf(s.z+b.z,0.f); s.w = fmaxf(s.w+b.w,0.f);
        ((float4*)out_co)[i4] = s;
    } else {
        int e = (blockIdx.x-50)*256 + threadIdx.x;
        if (e >= 5700) return;
        float s = 0.f;
        #pragma unroll
        for (int z=0; z<4; z++) s += g_partS[z*5700 + e];
        out_sem[e] = s + bs[e % 57];
    }
}

// ---------------- launch ----------------
extern "C" void kernel_launch(void* const* d_in, const int* in_sizes, int n_in,
                              void* d_out, int out_size){
    const float* pf  = (const float*)d_in[0];
    const float* Wp  = (const float*)d_in[1];
    const float* bp  = (const float*)d_in[2];
    const float* Wx  = (const float*)d_in[3];
    const float* bx  = (const float*)d_in[4];
    const float* Wel = (const float*)d_in[5];
    const float* bel = (const float*)d_in[6];
    const float* Wee = (const float*)d_in[7];
    const float* bee = (const float*)d_in[8];
    const float* Wne = (const float*)d_in[9];
    const float* bne = (const float*)d_in[10];
    const float* Wc  = (const float*)d_in[11];
    const float* bc  = (const float*)d_in[12];
    const float* Ws  = (const float*)d_in[13];
    const float* bs  = (const float*)d_in[14];
    const float* Wc2 = (const float*)d_in[15];
    const float* bc2 = (const float*)d_in[16];

    float* out     = (float*)d_out;
    float* out_co  = out;
    float* out_sem = out + 51200;
    float* out_ex  = out + 56900;
    float* out_lg  = out + 57000;

    k_gemv_part<<<dim3(50,4),256>>>(pf, Wp);
    k_gemv_fin<<<100,128>>>(bp, Wx, bx, out_ex);
    k_gp<<<dim3(8,4,16),256>>>(5 | (5<<8) | (5<<16) | (5<<24), 512, 4,
                               Wel, Wel + 512*512, Wne, Wne + 512*512);
    k_red<<<200,256>>>(4, 4, 0, 1, 2, 3);
    k_el<<<dim3(100,13),256>>>(bel, Wee, bee, out_lg);
    k_ce<<<dim3(8,157),256>>>(Wne + 1024*512, Wne + (1540+1024)*512, bel);
    k_msg<<<100,512>>>(0, out_lg, Wne + 1536*512, bne);
    k_gp<<<dim3(8,4,8),256>>>(6 | (6<<8), 512, 4,
                              Wne + 1540*512, Wne + (1540+512)*512, Wne, Wne);
    k_red<<<100,256>>>(4, 2, 2, 3, 0, 0);
    k_msg<<<100,512>>>(1, out_lg, Wne + (1540+1536)*512, bne + 512);
    k_gp<<<dim3(8,4,8),256>>>(9, 1536, 8, Wc, Wc, Wc, Wc);
    k_redh<<<50,256>>>(8, bc);
    k_heads<<<dim3(9,4,4),256>>>(Wc2, Ws);
    k_out<<<73,256>>>(bc2, bs, out_co, out_sem);
}